// round 2
// baseline (speedup 1.0000x reference)
#include <cuda_runtime.h>
#include <math.h>

// Problem constants
#define BATCH 4
#define SEQ   4096
#define DMODEL 1024
#define MTOT  (BATCH * SEQ)          // 16384
#define SCALE_INV (1.0f / 32.0f)     // 1/sqrt(1024)

// GEMM tile config
#define BM 128
#define BN 64
#define BK 16
#define TM 8
#define TN 4
#define NTHREADS 256

// Scratch: Q,K,V packed [3][MTOT*DMODEL], S/P [BATCH*SEQ*SEQ]
__device__ float g_QKV[3 * MTOT * DMODEL];          // 192 MB
__device__ float g_S[(size_t)BATCH * SEQ * SEQ];    // 256 MB

// ---------------------------------------------------------------------------
// Kernel 1: QKV projection. C = A @ W^T + b  (NT gemm)
// A = x [MTOT, DMODEL], W = [DMODEL, DMODEL] row-major (out,in), per blockIdx.z
// ---------------------------------------------------------------------------
__global__ __launch_bounds__(NTHREADS)
void qkv_kernel(const float* __restrict__ x,
                const float* __restrict__ Wq, const float* __restrict__ bq,
                const float* __restrict__ Wk, const float* __restrict__ bk,
                const float* __restrict__ Wv, const float* __restrict__ bv)
{
    const int z = blockIdx.z;
    const float* W    = (z == 0) ? Wq : (z == 1) ? Wk : Wv;
    const float* bias = (z == 0) ? bq : (z == 1) ? bk : bv;
    float* out = g_QKV + (size_t)z * (MTOT * DMODEL);

    __shared__ float As[BK][BM];
    __shared__ float Bs[BK][BN];

    const int tid = threadIdx.x;
    const int tx = tid & 15;          // 0..15 -> N groups
    const int ty = tid >> 4;          // 0..15 -> M groups
    const int m0 = blockIdx.y * BM;
    const int n0 = blockIdx.x * BN;

    float acc[TM][TN];
    #pragma unroll
    for (int i = 0; i < TM; i++)
        #pragma unroll
        for (int j = 0; j < TN; j++) acc[i][j] = 0.0f;

    const int K = DMODEL;
    for (int k0 = 0; k0 < K; k0 += BK) {
        // A tile: 128x16 = 512 float4, 2 per thread, transposed store
        #pragma unroll
        for (int i = 0; i < 2; i++) {
            int f = tid + i * NTHREADS;
            int row = f >> 2, c4 = f & 3;
            float4 v = *(const float4*)&x[(size_t)(m0 + row) * K + k0 + c4 * 4];
            As[c4 * 4 + 0][row] = v.x;
            As[c4 * 4 + 1][row] = v.y;
            As[c4 * 4 + 2][row] = v.z;
            As[c4 * 4 + 3][row] = v.w;
        }
        // B tile (W rows = output features): 64x16 = 256 float4
        {
            int row = tid >> 2, c4 = tid & 3;
            float4 v = *(const float4*)&W[(size_t)(n0 + row) * K + k0 + c4 * 4];
            Bs[c4 * 4 + 0][row] = v.x;
            Bs[c4 * 4 + 1][row] = v.y;
            Bs[c4 * 4 + 2][row] = v.z;
            Bs[c4 * 4 + 3][row] = v.w;
        }
        __syncthreads();
        #pragma unroll
        for (int kk = 0; kk < BK; kk++) {
            float a[TM], b[TN];
            *(float4*)&a[0] = *(float4*)&As[kk][ty * TM];
            *(float4*)&a[4] = *(float4*)&As[kk][ty * TM + 4];
            *(float4*)&b[0] = *(float4*)&Bs[kk][tx * TN];
            #pragma unroll
            for (int i = 0; i < TM; i++)
                #pragma unroll
                for (int j = 0; j < TN; j++)
                    acc[i][j] = fmaf(a[i], b[j], acc[i][j]);
        }
        __syncthreads();
    }

    float4 bv4 = *(const float4*)&bias[n0 + tx * TN];
    #pragma unroll
    for (int i = 0; i < TM; i++) {
        float4 r = make_float4(acc[i][0] + bv4.x, acc[i][1] + bv4.y,
                               acc[i][2] + bv4.z, acc[i][3] + bv4.w);
        *(float4*)&out[(size_t)(m0 + ty * TM + i) * DMODEL + n0 + tx * TN] = r;
    }
}

// ---------------------------------------------------------------------------
// Kernel 2: scores S = Q @ K^T * (1/32), causal block skip (NT gemm per batch)
// ---------------------------------------------------------------------------
__global__ __launch_bounds__(NTHREADS)
void scores_kernel()
{
    const int b = blockIdx.z;
    const int m0 = blockIdx.y * BM;   // q rows
    const int n0 = blockIdx.x * BN;   // k cols
    if (n0 > m0 + BM - 1) return;     // fully masked block

    const float* Q = g_QKV + (size_t)0 * (MTOT * DMODEL) + (size_t)b * SEQ * DMODEL;
    const float* Km = g_QKV + (size_t)1 * (MTOT * DMODEL) + (size_t)b * SEQ * DMODEL;
    float* out = g_S + (size_t)b * SEQ * SEQ;

    __shared__ float As[BK][BM];
    __shared__ float Bs[BK][BN];

    const int tid = threadIdx.x;
    const int tx = tid & 15;
    const int ty = tid >> 4;

    float acc[TM][TN];
    #pragma unroll
    for (int i = 0; i < TM; i++)
        #pragma unroll
        for (int j = 0; j < TN; j++) acc[i][j] = 0.0f;

    const int K = DMODEL;
    for (int k0 = 0; k0 < K; k0 += BK) {
        #pragma unroll
        for (int i = 0; i < 2; i++) {
            int f = tid + i * NTHREADS;
            int row = f >> 2, c4 = f & 3;
            float4 v = *(const float4*)&Q[(size_t)(m0 + row) * K + k0 + c4 * 4];
            As[c4 * 4 + 0][row] = v.x;
            As[c4 * 4 + 1][row] = v.y;
            As[c4 * 4 + 2][row] = v.z;
            As[c4 * 4 + 3][row] = v.w;
        }
        {
            int row = tid >> 2, c4 = tid & 3;
            float4 v = *(const float4*)&Km[(size_t)(n0 + row) * K + k0 + c4 * 4];
            Bs[c4 * 4 + 0][row] = v.x;
            Bs[c4 * 4 + 1][row] = v.y;
            Bs[c4 * 4 + 2][row] = v.z;
            Bs[c4 * 4 + 3][row] = v.w;
        }
        __syncthreads();
        #pragma unroll
        for (int kk = 0; kk < BK; kk++) {
            float a[TM], bb[TN];
            *(float4*)&a[0] = *(float4*)&As[kk][ty * TM];
            *(float4*)&a[4] = *(float4*)&As[kk][ty * TM + 4];
            *(float4*)&bb[0] = *(float4*)&Bs[kk][tx * TN];
            #pragma unroll
            for (int i = 0; i < TM; i++)
                #pragma unroll
                for (int j = 0; j < TN; j++)
                    acc[i][j] = fmaf(a[i], bb[j], acc[i][j]);
        }
        __syncthreads();
    }

    #pragma unroll
    for (int i = 0; i < TM; i++) {
        float4 r = make_float4(acc[i][0] * SCALE_INV, acc[i][1] * SCALE_INV,
                               acc[i][2] * SCALE_INV, acc[i][3] * SCALE_INV);
        *(float4*)&out[(size_t)(m0 + ty * TM + i) * SEQ + n0 + tx * TN] = r;
    }
}

// ---------------------------------------------------------------------------
// Kernel 3: row softmax over k<=q; zero-fill k>q
// ---------------------------------------------------------------------------
__global__ __launch_bounds__(256)
void softmax_kernel()
{
    const int r = blockIdx.x;               // 0..MTOT-1
    const int b = r >> 12;                  // /4096
    const int q = r & (SEQ - 1);
    float* row = g_S + (size_t)b * SEQ * SEQ + (size_t)q * SEQ;
    const int len = q + 1;
    const int tid = threadIdx.x;

    __shared__ float red[256];

    float m = -INFINITY;
    for (int k = tid; k < len; k += 256) m = fmaxf(m, row[k]);
    red[tid] = m;
    __syncthreads();
    #pragma unroll
    for (int s = 128; s > 0; s >>= 1) {
        if (tid < s) red[tid] = fmaxf(red[tid], red[tid + s]);
        __syncthreads();
    }
    m = red[0];
    __syncthreads();

    float sum = 0.0f;
    for (int k = tid; k < len; k += 256) {
        float e = __expf(row[k] - m);
        row[k] = e;
        sum += e;
    }
    red[tid] = sum;
    __syncthreads();
    #pragma unroll
    for (int s = 128; s > 0; s >>= 1) {
        if (tid < s) red[tid] += red[tid + s];
        __syncthreads();
    }
    const float inv = 1.0f / red[0];
    __syncthreads();

    for (int k = tid; k < len; k += 256) row[k] *= inv;
    for (int k = len + tid; k < SEQ; k += 256) row[k] = 0.0f;
}

// ---------------------------------------------------------------------------
// Kernel 4: O = P @ V  (NN gemm per batch, k-loop truncated at causal bound)
// ---------------------------------------------------------------------------
__global__ __launch_bounds__(NTHREADS)
void pv_kernel(float* __restrict__ out_all)
{
    const int b = blockIdx.z;
    const int m0 = blockIdx.y * BM;   // q rows
    const int n0 = blockIdx.x * BN;   // d cols

    const float* P = g_S + (size_t)b * SEQ * SEQ;
    const float* V = g_QKV + (size_t)2 * (MTOT * DMODEL) + (size_t)b * SEQ * DMODEL;
    float* out = out_all + (size_t)b * SEQ * DMODEL;

    __shared__ float As[BK][BM];
    __shared__ float Bs[BK][BN];

    const int tid = threadIdx.x;
    const int tx = tid & 15;
    const int ty = tid >> 4;

    float acc[TM][TN];
    #pragma unroll
    for (int i = 0; i < TM; i++)
        #pragma unroll
        for (int j = 0; j < TN; j++) acc[i][j] = 0.0f;

    const int kend = m0 + BM;         // causal: rows in this tile need k < m0+BM
    for (int k0 = 0; k0 < kend; k0 += BK) {
        // P tile (A): 128x16, transposed store
        #pragma unroll
        for (int i = 0; i < 2; i++) {
            int f = tid + i * NTHREADS;
            int row = f >> 2, c4 = f & 3;
            float4 v = *(const float4*)&P[(size_t)(m0 + row) * SEQ + k0 + c4 * 4];
            As[c4 * 4 + 0][row] = v.x;
            As[c4 * 4 + 1][row] = v.y;
            As[c4 * 4 + 2][row] = v.z;
            As[c4 * 4 + 3][row] = v.w;
        }
        // V tile (B, NN): 16 rows x 64 cols = 256 float4
        {
            int row = tid >> 4, c4 = tid & 15;
            float4 v = *(const float4*)&V[(size_t)(k0 + row) * DMODEL + n0 + c4 * 4];
            *(float4*)&Bs[row][c4 * 4] = v;
        }
        __syncthreads();
        #pragma unroll
        for (int kk = 0; kk < BK; kk++) {
            float a[TM], bb[TN];
            *(float4*)&a[0] = *(float4*)&As[kk][ty * TM];
            *(float4*)&a[4] = *(float4*)&As[kk][ty * TM + 4];
            *(float4*)&bb[0] = *(float4*)&Bs[kk][tx * TN];
            #pragma unroll
            for (int i = 0; i < TM; i++)
                #pragma unroll
                for (int j = 0; j < TN; j++)
                    acc[i][j] = fmaf(a[i], bb[j], acc[i][j]);
        }
        __syncthreads();
    }

    #pragma unroll
    for (int i = 0; i < TM; i++) {
        float4 r = make_float4(acc[i][0], acc[i][1], acc[i][2], acc[i][3]);
        *(float4*)&out[(size_t)(m0 + ty * TM + i) * DMODEL + n0 + tx * TN] = r;
    }
}

// ---------------------------------------------------------------------------
extern "C" void kernel_launch(void* const* d_in, const int* in_sizes, int n_in,
                              void* d_out, int out_size)
{
    const float* x  = (const float*)d_in[0];
    const float* Wq = (const float*)d_in[1];
    const float* bq = (const float*)d_in[2];
    const float* Wk = (const float*)d_in[3];
    const float* bk = (const float*)d_in[4];
    const float* Wv = (const float*)d_in[5];
    const float* bv = (const float*)d_in[6];
    float* out = (float*)d_out;

    dim3 thr(NTHREADS);

    // 1) QKV projections
    {
        dim3 grid(DMODEL / BN, MTOT / BM, 3);   // (16, 128, 3)
        qkv_kernel<<<grid, thr>>>(x, Wq, bq, Wk, bk, Wv, bv);
    }
    // 2) scores
    {
        dim3 grid(SEQ / BN, SEQ / BM, BATCH);   // (64, 32, 4)
        scores_kernel<<<grid, thr>>>();
    }
    // 3) softmax
    {
        softmax_kernel<<<MTOT, 256>>>();
    }
    // 4) P @ V
    {
        dim3 grid(DMODEL / BN, SEQ / BM, BATCH); // (16, 32, 4)
        pv_kernel<<<grid, thr>>>(out);
    }
}

// round 3
// speedup vs baseline: 3.2217x; 3.2217x over previous
#include <cuda_runtime.h>
#include <math.h>
#include <stdint.h>

// Problem constants
#define BATCH 4
#define SEQ   4096
#define DMODEL 1024
#define MTOT  (BATCH * SEQ)          // 16384
#define SCALE_INV (1.0f / 32.0f)     // 1/sqrt(1024)

// Tile config
#define BM 128
#define BN 128
#define BK 32
#define NTHREADS 256
#define LDA  36    // BK + 4  (stride ≡ 4 mod 32 -> conflict-free frags)
#define LDB2 136   // BN + 8  (stride ≡ 8 mod 32 -> conflict-free NN frags)

// Scratch
__device__ float g_QKV[3 * MTOT * DMODEL];          // 192 MB
__device__ float g_S[(size_t)BATCH * SEQ * SEQ];    // 256 MB

// ---------------------------------------------------------------------------
// TF32 helpers
// ---------------------------------------------------------------------------
__device__ __forceinline__ float to_tf32(float x) {
    float r; asm("cvt.rna.tf32.f32 %0, %1;" : "=f"(r) : "f"(x)); return r;
}
__device__ __forceinline__ float4 to_tf32x4(float4 v) {
    return make_float4(to_tf32(v.x), to_tf32(v.y), to_tf32(v.z), to_tf32(v.w));
}
__device__ __forceinline__ void mma_tf32(float* c, const uint32_t* a, const uint32_t* b) {
    asm volatile(
        "mma.sync.aligned.m16n8k8.row.col.f32.tf32.tf32.f32 "
        "{%0,%1,%2,%3}, {%4,%5,%6,%7}, {%8,%9}, {%0,%1,%2,%3};"
        : "+f"(c[0]), "+f"(c[1]), "+f"(c[2]), "+f"(c[3])
        : "r"(a[0]), "r"(a[1]), "r"(a[2]), "r"(a[3]), "r"(b[0]), "r"(b[1]));
}

// Load 128x32 tile, rows contiguous in K (NT operand), convert to tf32.
__device__ __forceinline__ void load_tile_nt(float* Sdst, const float* G,
                                             int row0, int k0, int ldg, int tid) {
    #pragma unroll
    for (int i = 0; i < 4; i++) {
        int f = tid + i * NTHREADS;
        int row = f >> 3;            // 8 float4 per row
        int c4 = (f & 7) * 4;
        float4 v = *(const float4*)&G[(size_t)(row0 + row) * ldg + k0 + c4];
        *(float4*)&Sdst[row * LDA + c4] = to_tf32x4(v);
    }
}

// Load 32x128 tile (NN B operand: rows = k, cols = n), convert to tf32.
__device__ __forceinline__ void load_tile_nn(float* Sdst, const float* G,
                                             int k0, int n0, int ldg, int tid) {
    #pragma unroll
    for (int i = 0; i < 4; i++) {
        int f = tid + i * NTHREADS;
        int row = f >> 5;            // 32 float4 per row
        int c4 = (f & 31) * 4;
        float4 v = *(const float4*)&G[(size_t)(k0 + row) * ldg + n0 + c4];
        *(float4*)&Sdst[row * LDB2 + c4] = to_tf32x4(v);
    }
}

// MMA over one BK=32 chunk, NT layout (As[m][k], Bs[n][k], both stride LDA).
__device__ __forceinline__ void mma_block_nt(const float* As, const float* Bs,
                                             float c[4][4][4], int wm, int wn, int lane) {
    const uint32_t* Au = (const uint32_t*)As;
    const uint32_t* Bu = (const uint32_t*)Bs;
    const int gr = lane >> 2;   // 0..7
    const int gc = lane & 3;    // 0..3
    #pragma unroll
    for (int ks = 0; ks < 4; ks++) {
        const int k8 = ks * 8;
        uint32_t a[4][4], b[4][2];
        const int ac = k8 + gc;
        #pragma unroll
        for (int i = 0; i < 4; i++) {
            int ar = wm + i * 16 + gr;
            a[i][0] = Au[ar * LDA + ac];
            a[i][1] = Au[(ar + 8) * LDA + ac];
            a[i][2] = Au[ar * LDA + ac + 4];
            a[i][3] = Au[(ar + 8) * LDA + ac + 4];
        }
        #pragma unroll
        for (int j = 0; j < 4; j++) {
            int br = wn + j * 8 + gr;
            b[j][0] = Bu[br * LDA + ac];
            b[j][1] = Bu[br * LDA + ac + 4];
        }
        #pragma unroll
        for (int i = 0; i < 4; i++)
            #pragma unroll
            for (int j = 0; j < 4; j++)
                mma_tf32(c[i][j], a[i], b[j]);
    }
}

// MMA over one BK=32 chunk, NN layout (As[m][k] stride LDA, Bs2[k][n] stride LDB2).
__device__ __forceinline__ void mma_block_nn(const float* As, const float* Bs2,
                                             float c[4][4][4], int wm, int wn, int lane) {
    const uint32_t* Au = (const uint32_t*)As;
    const uint32_t* Bu = (const uint32_t*)Bs2;
    const int gr = lane >> 2;
    const int gc = lane & 3;
    #pragma unroll
    for (int ks = 0; ks < 4; ks++) {
        const int k8 = ks * 8;
        uint32_t a[4][4], b[4][2];
        const int ac = k8 + gc;
        #pragma unroll
        for (int i = 0; i < 4; i++) {
            int ar = wm + i * 16 + gr;
            a[i][0] = Au[ar * LDA + ac];
            a[i][1] = Au[(ar + 8) * LDA + ac];
            a[i][2] = Au[ar * LDA + ac + 4];
            a[i][3] = Au[(ar + 8) * LDA + ac + 4];
        }
        const int bn = wn + gr;
        #pragma unroll
        for (int j = 0; j < 4; j++) {
            b[j][0] = Bu[(k8 + gc) * LDB2 + bn + j * 8];
            b[j][1] = Bu[(k8 + 4 + gc) * LDB2 + bn + j * 8];
        }
        #pragma unroll
        for (int i = 0; i < 4; i++)
            #pragma unroll
            for (int j = 0; j < 4; j++)
                mma_tf32(c[i][j], a[i], b[j]);
    }
}

// ---------------------------------------------------------------------------
// Kernel 1: QKV projection. out = x @ W^T + b   (NT, tf32)
// ---------------------------------------------------------------------------
__global__ __launch_bounds__(NTHREADS)
void qkv_kernel(const float* __restrict__ x,
                const float* __restrict__ Wq, const float* __restrict__ bq,
                const float* __restrict__ Wk, const float* __restrict__ bk,
                const float* __restrict__ Wv, const float* __restrict__ bv)
{
    const int z = blockIdx.z;
    const float* W    = (z == 0) ? Wq : (z == 1) ? Wk : Wv;
    const float* bias = (z == 0) ? bq : (z == 1) ? bk : bv;
    float* out = g_QKV + (size_t)z * (MTOT * DMODEL);

    __shared__ float As[BM * LDA];
    __shared__ float Bs[BN * LDA];

    const int tid  = threadIdx.x;
    const int lane = tid & 31;
    const int warp = tid >> 5;
    const int wm = (warp & 1) * 64;
    const int wn = (warp >> 1) * 32;
    const int m0 = blockIdx.y * BM;
    const int n0 = blockIdx.x * BN;

    float c[4][4][4];
    #pragma unroll
    for (int i = 0; i < 4; i++)
        #pragma unroll
        for (int j = 0; j < 4; j++)
            #pragma unroll
            for (int t = 0; t < 4; t++) c[i][j][t] = 0.0f;

    for (int k0 = 0; k0 < DMODEL; k0 += BK) {
        load_tile_nt(As, x, m0, k0, DMODEL, tid);
        load_tile_nt(Bs, W, n0, k0, DMODEL, tid);
        __syncthreads();
        mma_block_nt(As, Bs, c, wm, wn, lane);
        __syncthreads();
    }

    const int gr = lane >> 2, gc = lane & 3;
    #pragma unroll
    for (int i = 0; i < 4; i++) {
        int r0 = m0 + wm + i * 16 + gr;
        #pragma unroll
        for (int j = 0; j < 4; j++) {
            int cn = n0 + wn + j * 8 + gc * 2;
            float2 bb = *(const float2*)&bias[cn];
            *(float2*)&out[(size_t)r0 * DMODEL + cn] =
                make_float2(c[i][j][0] + bb.x, c[i][j][1] + bb.y);
            *(float2*)&out[(size_t)(r0 + 8) * DMODEL + cn] =
                make_float2(c[i][j][2] + bb.x, c[i][j][3] + bb.y);
        }
    }
}

// ---------------------------------------------------------------------------
// Kernel 2: scores S = Q @ K^T * (1/32), causal block skip (NT, tf32)
// ---------------------------------------------------------------------------
__global__ __launch_bounds__(NTHREADS)
void scores_kernel()
{
    const int b  = blockIdx.z;
    const int m0 = blockIdx.y * BM;
    const int n0 = blockIdx.x * BN;
    if (n0 > m0) return;   // fully masked block

    const float* Q  = g_QKV + (size_t)b * SEQ * DMODEL;
    const float* Km = g_QKV + (size_t)(MTOT * DMODEL) + (size_t)b * SEQ * DMODEL;
    float* out = g_S + (size_t)b * SEQ * SEQ;

    __shared__ float As[BM * LDA];
    __shared__ float Bs[BN * LDA];

    const int tid  = threadIdx.x;
    const int lane = tid & 31;
    const int warp = tid >> 5;
    const int wm = (warp & 1) * 64;
    const int wn = (warp >> 1) * 32;

    float c[4][4][4];
    #pragma unroll
    for (int i = 0; i < 4; i++)
        #pragma unroll
        for (int j = 0; j < 4; j++)
            #pragma unroll
            for (int t = 0; t < 4; t++) c[i][j][t] = 0.0f;

    for (int k0 = 0; k0 < DMODEL; k0 += BK) {
        load_tile_nt(As, Q,  m0, k0, DMODEL, tid);
        load_tile_nt(Bs, Km, n0, k0, DMODEL, tid);
        __syncthreads();
        mma_block_nt(As, Bs, c, wm, wn, lane);
        __syncthreads();
    }

    const int gr = lane >> 2, gc = lane & 3;
    #pragma unroll
    for (int i = 0; i < 4; i++) {
        int r0 = m0 + wm + i * 16 + gr;
        #pragma unroll
        for (int j = 0; j < 4; j++) {
            int cn = n0 + wn + j * 8 + gc * 2;
            *(float2*)&out[(size_t)r0 * SEQ + cn] =
                make_float2(c[i][j][0] * SCALE_INV, c[i][j][1] * SCALE_INV);
            *(float2*)&out[(size_t)(r0 + 8) * SEQ + cn] =
                make_float2(c[i][j][2] * SCALE_INV, c[i][j][3] * SCALE_INV);
        }
    }
}

// ---------------------------------------------------------------------------
// Kernel 3: row softmax over k<=q; zero-fill k>q (fp32)
// ---------------------------------------------------------------------------
__global__ __launch_bounds__(256)
void softmax_kernel()
{
    const int r = blockIdx.x;
    const int b = r >> 12;
    const int q = r & (SEQ - 1);
    float* row = g_S + (size_t)b * SEQ * SEQ + (size_t)q * SEQ;
    const int len = q + 1;
    const int tid = threadIdx.x;

    __shared__ float red[256];

    float m = -INFINITY;
    for (int k = tid; k < len; k += 256) m = fmaxf(m, row[k]);
    red[tid] = m;
    __syncthreads();
    #pragma unroll
    for (int s = 128; s > 0; s >>= 1) {
        if (tid < s) red[tid] = fmaxf(red[tid], red[tid + s]);
        __syncthreads();
    }
    m = red[0];
    __syncthreads();

    float sum = 0.0f;
    for (int k = tid; k < len; k += 256) {
        float e = __expf(row[k] - m);
        row[k] = e;
        sum += e;
    }
    red[tid] = sum;
    __syncthreads();
    #pragma unroll
    for (int s = 128; s > 0; s >>= 1) {
        if (tid < s) red[tid] += red[tid + s];
        __syncthreads();
    }
    const float inv = 1.0f / red[0];
    __syncthreads();

    for (int k = tid; k < len; k += 256) row[k] *= inv;
    for (int k = len + tid; k < SEQ; k += 256) row[k] = 0.0f;
}

// ---------------------------------------------------------------------------
// Kernel 4: O = P @ V  (NN, tf32, k-loop truncated at causal bound)
// ---------------------------------------------------------------------------
__global__ __launch_bounds__(NTHREADS)
void pv_kernel(float* __restrict__ out_all)
{
    const int b  = blockIdx.z;
    const int m0 = blockIdx.y * BM;
    const int n0 = blockIdx.x * BN;

    const float* P = g_S + (size_t)b * SEQ * SEQ;
    const float* V = g_QKV + (size_t)2 * (MTOT * DMODEL) + (size_t)b * SEQ * DMODEL;
    float* out = out_all + (size_t)b * SEQ * DMODEL;

    __shared__ float As[BM * LDA];
    __shared__ float Bs2[BK * LDB2];

    const int tid  = threadIdx.x;
    const int lane = tid & 31;
    const int warp = tid >> 5;
    const int wm = (warp & 1) * 64;
    const int wn = (warp >> 1) * 32;

    float c[4][4][4];
    #pragma unroll
    for (int i = 0; i < 4; i++)
        #pragma unroll
        for (int j = 0; j < 4; j++)
            #pragma unroll
            for (int t = 0; t < 4; t++) c[i][j][t] = 0.0f;

    const int kend = m0 + BM;   // causal truncation
    for (int k0 = 0; k0 < kend; k0 += BK) {
        load_tile_nt(As, P, m0, k0, SEQ, tid);
        load_tile_nn(Bs2, V, k0, n0, DMODEL, tid);
        __syncthreads();
        mma_block_nn(As, Bs2, c, wm, wn, lane);
        __syncthreads();
    }

    const int gr = lane >> 2, gc = lane & 3;
    #pragma unroll
    for (int i = 0; i < 4; i++) {
        int r0 = m0 + wm + i * 16 + gr;
        #pragma unroll
        for (int j = 0; j < 4; j++) {
            int cn = n0 + wn + j * 8 + gc * 2;
            *(float2*)&out[(size_t)r0 * DMODEL + cn] =
                make_float2(c[i][j][0], c[i][j][1]);
            *(float2*)&out[(size_t)(r0 + 8) * DMODEL + cn] =
                make_float2(c[i][j][2], c[i][j][3]);
        }
    }
}

// ---------------------------------------------------------------------------
extern "C" void kernel_launch(void* const* d_in, const int* in_sizes, int n_in,
                              void* d_out, int out_size)
{
    const float* x  = (const float*)d_in[0];
    const float* Wq = (const float*)d_in[1];
    const float* bq = (const float*)d_in[2];
    const float* Wk = (const float*)d_in[3];
    const float* bk = (const float*)d_in[4];
    const float* Wv = (const float*)d_in[5];
    const float* bv = (const float*)d_in[6];
    float* out = (float*)d_out;

    dim3 thr(NTHREADS);

    {   // 1) QKV projections
        dim3 grid(DMODEL / BN, MTOT / BM, 3);    // (8, 128, 3)
        qkv_kernel<<<grid, thr>>>(x, Wq, bq, Wk, bk, Wv, bv);
    }
    {   // 2) scores
        dim3 grid(SEQ / BN, SEQ / BM, BATCH);    // (32, 32, 4)
        scores_kernel<<<grid, thr>>>();
    }
    {   // 3) softmax
        softmax_kernel<<<MTOT, 256>>>();
    }
    {   // 4) P @ V
        dim3 grid(DMODEL / BN, SEQ / BM, BATCH); // (8, 32, 4)
        pv_kernel<<<grid, thr>>>(out);
    }
}